// round 1
// baseline (speedup 1.0000x reference)
#include <cuda_runtime.h>
#include <math.h>

#define B_ROWS 8192
#define D_DIM  1024
#define HR_DIM 512
#define HE_DIM 4096
#define HF_DIM 2048

// ---------------- scratch (static __device__, no allocation) ----------------
__device__ float g_H[B_ROWS * HR_DIM];       // router hidden
__device__ float g_Y1[B_ROWS * HE_DIM];      // expert hidden (rows disjoint per expert)
__device__ float g_FUSED[B_ROWS * D_DIM];    // w * selected
__device__ float g_G[B_ROWS * HF_DIM];       // fusion hidden
__device__ float g_w[B_ROWS];                // routing weight of chosen expert
__device__ int   g_hint[B_ROWS];             // emb row (math_op or lang_task)
__device__ int   g_list[2 * B_ROWS];         // compacted row ids per expert
__device__ int   g_cnt[2];

__global__ void reset_kernel() {
    if (threadIdx.x < 2) g_cnt[threadIdx.x] = 0;
}

// ---------------- router head: warp per row ----------------
__global__ void router_head_kernel(const float* __restrict__ Wdom,
                                   const float* __restrict__ bdom,
                                   const float* __restrict__ Wmop,
                                   const float* __restrict__ Wlt) {
    int warp = (blockIdx.x * blockDim.x + threadIdx.x) >> 5;
    int lane = threadIdx.x & 31;
    if (warp >= B_ROWS) return;
    const float* h = g_H + (size_t)warp * HR_DIM;
    float a0 = 0.f, a1 = 0.f;
    float m0 = 0.f, m1 = 0.f, m2 = 0.f, m3 = 0.f;
    float l0 = 0.f, l1 = 0.f, l2 = 0.f, l3 = 0.f;
    for (int i = lane; i < HR_DIM; i += 32) {
        float hv = h[i];
        a0 += hv * Wdom[i * 2 + 0];
        a1 += hv * Wdom[i * 2 + 1];
        m0 += hv * Wmop[i * 4 + 0];
        m1 += hv * Wmop[i * 4 + 1];
        m2 += hv * Wmop[i * 4 + 2];
        m3 += hv * Wmop[i * 4 + 3];
        l0 += hv * Wlt[i * 4 + 0];
        l1 += hv * Wlt[i * 4 + 1];
        l2 += hv * Wlt[i * 4 + 2];
        l3 += hv * Wlt[i * 4 + 3];
    }
#pragma unroll
    for (int off = 16; off > 0; off >>= 1) {
        a0 += __shfl_down_sync(0xffffffffu, a0, off);
        a1 += __shfl_down_sync(0xffffffffu, a1, off);
        m0 += __shfl_down_sync(0xffffffffu, m0, off);
        m1 += __shfl_down_sync(0xffffffffu, m1, off);
        m2 += __shfl_down_sync(0xffffffffu, m2, off);
        m3 += __shfl_down_sync(0xffffffffu, m3, off);
        l0 += __shfl_down_sync(0xffffffffu, l0, off);
        l1 += __shfl_down_sync(0xffffffffu, l1, off);
        l2 += __shfl_down_sync(0xffffffffu, l2, off);
        l3 += __shfl_down_sync(0xffffffffu, l3, off);
    }
    if (lane == 0) {
        a0 += bdom[0];
        a1 += bdom[1];
        int primary = (a1 > a0) ? 1 : 0;  // argmax, first-max wins ties
        float lp = primary ? a1 : a0;
        float lo = primary ? a0 : a1;
        float w = 1.f / (1.f + expf(lo - lp));  // softmax weight of chosen expert
        int mop = 0; float best = m0;
        if (m1 > best) { best = m1; mop = 1; }
        if (m2 > best) { best = m2; mop = 2; }
        if (m3 > best) { best = m3; mop = 3; }
        int lt = 0; best = l0;
        if (l1 > best) { best = l1; lt = 1; }
        if (l2 > best) { best = l2; lt = 2; }
        if (l3 > best) { best = l3; lt = 3; }
        g_w[warp] = w;
        g_hint[warp] = primary ? lt : mop;
        int pos = atomicAdd(&g_cnt[primary], 1);
        g_list[primary * B_ROWS + pos] = warp;
    }
}

// ---------------- fp32 GEMM: C = epilogue(A @ W + bias) ----------------
// BM=BN=128, BK=8, 256 threads, 8x8 microtile.
// GATHER: row ids via rowlist (count via cntPtr), A rows gathered, C rows scattered.
// ADD_EMB: A row += emb[g_hint[row]]
// RELU / SCALE (w[row]*(dot+bias)) / RESID (+= resid[row])
template <bool GATHER, bool ADD_EMB, bool RELU, bool SCALE, bool RESID>
__global__ __launch_bounds__(256, 2) void gemm128_kernel(
    const float* __restrict__ A, const float* __restrict__ W,
    const float* __restrict__ bias, float* __restrict__ C,
    const float* __restrict__ resid, int N, int K,
    const int* __restrict__ rowlist, const int* __restrict__ cntPtr,
    const float* __restrict__ emb) {
    const int BM = 128, BN = 128, BK = 8;
    __shared__ float As[BK][BM];
    __shared__ float Bs[BK][BN];
    __shared__ int   rmap[BM];
    __shared__ float rsc[BM];

    int tid = threadIdx.x;
    int tile_m = blockIdx.y * BM;
    int tile_n = blockIdx.x * BN;

    int cnt = B_ROWS;
    if (GATHER) {
        cnt = *cntPtr;
        if (tile_m >= cnt) return;
    }
    if (tid < BM) {
        int m = tile_m + tid;
        int r;
        if (GATHER) r = (m < cnt) ? rowlist[m] : -1;
        else        r = m;
        rmap[tid] = r;
        if (SCALE) rsc[tid] = (r >= 0) ? g_w[r] : 0.f;
    }
    __syncthreads();

    int tx = tid & 15;   // col group
    int ty = tid >> 4;   // row group
    int arow = tid >> 1;
    int akq = (tid & 1) * 4;
    int bkr = tid >> 5;
    int bc = (tid & 31) * 4;

    int r_a = rmap[arow];
    const float* aptr = (r_a >= 0) ? (A + (size_t)r_a * K + akq) : nullptr;
    const float* eptr = nullptr;
    if (ADD_EMB && r_a >= 0) eptr = emb + (size_t)g_hint[r_a] * K + akq;

    float acc[8][8];
#pragma unroll
    for (int i = 0; i < 8; i++)
#pragma unroll
        for (int j = 0; j < 8; j++) acc[i][j] = 0.f;

    for (int k0 = 0; k0 < K; k0 += BK) {
        float4 av = make_float4(0.f, 0.f, 0.f, 0.f);
        if (r_a >= 0) {
            av = *reinterpret_cast<const float4*>(aptr + k0);
            if (ADD_EMB) {
                float4 ev = *reinterpret_cast<const float4*>(eptr + k0);
                av.x += ev.x; av.y += ev.y; av.z += ev.z; av.w += ev.w;
            }
        }
        float4 bv = *reinterpret_cast<const float4*>(W + (size_t)(k0 + bkr) * N + tile_n + bc);
        __syncthreads();
        As[akq + 0][arow] = av.x;
        As[akq + 1][arow] = av.y;
        As[akq + 2][arow] = av.z;
        As[akq + 3][arow] = av.w;
        *reinterpret_cast<float4*>(&Bs[bkr][bc]) = bv;
        __syncthreads();
#pragma unroll
        for (int kk = 0; kk < BK; kk++) {
            float4 a0v = *reinterpret_cast<const float4*>(&As[kk][ty * 8]);
            float4 a1v = *reinterpret_cast<const float4*>(&As[kk][ty * 8 + 4]);
            float4 b0v = *reinterpret_cast<const float4*>(&Bs[kk][tx * 8]);
            float4 b1v = *reinterpret_cast<const float4*>(&Bs[kk][tx * 8 + 4]);
            float aa[8] = {a0v.x, a0v.y, a0v.z, a0v.w, a1v.x, a1v.y, a1v.z, a1v.w};
            float bb[8] = {b0v.x, b0v.y, b0v.z, b0v.w, b1v.x, b1v.y, b1v.z, b1v.w};
#pragma unroll
            for (int i = 0; i < 8; i++)
#pragma unroll
                for (int j = 0; j < 8; j++) acc[i][j] += aa[i] * bb[j];
        }
    }

    // epilogue
    float bfrag[8];
#pragma unroll
    for (int j = 0; j < 8; j++) bfrag[j] = bias[tile_n + tx * 8 + j];
#pragma unroll
    for (int i = 0; i < 8; i++) {
        int r = rmap[ty * 8 + i];
        if (r < 0) continue;
        float sc = SCALE ? rsc[ty * 8 + i] : 1.f;
        size_t off = (size_t)r * N + tile_n + tx * 8;
        float v[8];
#pragma unroll
        for (int j = 0; j < 8; j++) {
            float t = acc[i][j] + bfrag[j];
            if (RELU) t = fmaxf(t, 0.f);
            if (SCALE) t *= sc;
            v[j] = t;
        }
        if (RESID) {
            float4 r0 = *reinterpret_cast<const float4*>(resid + off);
            float4 r1 = *reinterpret_cast<const float4*>(resid + off + 4);
            v[0] += r0.x; v[1] += r0.y; v[2] += r0.z; v[3] += r0.w;
            v[4] += r1.x; v[5] += r1.y; v[6] += r1.z; v[7] += r1.w;
        }
        *reinterpret_cast<float4*>(C + off)     = make_float4(v[0], v[1], v[2], v[3]);
        *reinterpret_cast<float4*>(C + off + 4) = make_float4(v[4], v[5], v[6], v[7]);
    }
}

// ---------------- launch ----------------
extern "C" void kernel_launch(void* const* d_in, const int* in_sizes, int n_in,
                              void* d_out, int out_size) {
    const float* x       = (const float*)d_in[0];
    const float* W_r1    = (const float*)d_in[1];
    const float* b_r1    = (const float*)d_in[2];
    const float* W_dom   = (const float*)d_in[3];
    const float* b_dom   = (const float*)d_in[4];
    const float* W_mop   = (const float*)d_in[5];
    const float* W_lt    = (const float*)d_in[6];
    const float* op_emb  = (const float*)d_in[7];
    const float* W_m1    = (const float*)d_in[8];
    const float* b_m1    = (const float*)d_in[9];
    const float* W_m2    = (const float*)d_in[10];
    const float* b_m2    = (const float*)d_in[11];
    const float* task_emb= (const float*)d_in[12];
    const float* W_l1    = (const float*)d_in[13];
    const float* b_l1    = (const float*)d_in[14];
    const float* W_l2    = (const float*)d_in[15];
    const float* b_l2    = (const float*)d_in[16];
    const float* W_f1    = (const float*)d_in[17];
    const float* b_f1    = (const float*)d_in[18];
    const float* W_f2    = (const float*)d_in[19];
    const float* b_f2    = (const float*)d_in[20];
    float* out = (float*)d_out;

    float *H, *Y1, *FUSED, *G;
    int *list, *cnt;
    cudaGetSymbolAddress((void**)&H, g_H);
    cudaGetSymbolAddress((void**)&Y1, g_Y1);
    cudaGetSymbolAddress((void**)&FUSED, g_FUSED);
    cudaGetSymbolAddress((void**)&G, g_G);
    cudaGetSymbolAddress((void**)&list, g_list);
    cudaGetSymbolAddress((void**)&cnt, g_cnt);

    dim3 blk(256);
    int mtiles = B_ROWS / 128;

    reset_kernel<<<1, 32>>>();

    // router GEMM: H = relu(x @ W_r1 + b_r1)
    gemm128_kernel<false, false, true, false, false>
        <<<dim3(HR_DIM / 128, mtiles), blk>>>(x, W_r1, b_r1, H, nullptr,
                                              HR_DIM, D_DIM, nullptr, nullptr, nullptr);
    // router head + compaction
    router_head_kernel<<<B_ROWS / 8, 256>>>(W_dom, b_dom, W_mop, W_lt);

    // expert pass 1: Y1[r] = relu((x[r] + emb[hint[r]]) @ W1 + b1)
    gemm128_kernel<true, true, true, false, false>
        <<<dim3(HE_DIM / 128, mtiles), blk>>>(x, W_m1, b_m1, Y1, nullptr,
                                              HE_DIM, D_DIM, list, cnt, op_emb);
    gemm128_kernel<true, true, true, false, false>
        <<<dim3(HE_DIM / 128, mtiles), blk>>>(x, W_l1, b_l1, Y1, nullptr,
                                              HE_DIM, D_DIM, list + B_ROWS, cnt + 1, task_emb);

    // expert pass 2: FUSED[r] = w[r] * (Y1[r] @ W2 + b2)
    gemm128_kernel<true, false, false, true, false>
        <<<dim3(D_DIM / 128, mtiles), blk>>>(Y1, W_m2, b_m2, FUSED, nullptr,
                                             D_DIM, HE_DIM, list, cnt, nullptr);
    gemm128_kernel<true, false, false, true, false>
        <<<dim3(D_DIM / 128, mtiles), blk>>>(Y1, W_l2, b_l2, FUSED, nullptr,
                                             D_DIM, HE_DIM, list + B_ROWS, cnt + 1, nullptr);

    // fusion: G = relu(FUSED @ W_f1 + b_f1)
    gemm128_kernel<false, false, true, false, false>
        <<<dim3(HF_DIM / 128, mtiles), blk>>>(FUSED, W_f1, b_f1, G, nullptr,
                                              HF_DIM, D_DIM, nullptr, nullptr, nullptr);
    // final: out = FUSED + G @ W_f2 + b_f2
    gemm128_kernel<false, false, false, false, true>
        <<<dim3(D_DIM / 128, mtiles), blk>>>(G, W_f2, b_f2, out, FUSED,
                                             D_DIM, HF_DIM, nullptr, nullptr, nullptr);
}